// round 13
// baseline (speedup 1.0000x reference)
#include <cuda_runtime.h>
#include <math.h>
#include <stdint.h>

#define SEQ 20
#define H   128
#define NC  100000

typedef unsigned long long u64;

// ---------------- device scratch (no allocations allowed) ----------------
__device__ float g_xg[2][SEQ][4 * H];    // fwd/bwd gate pre-activations from x (+both biases)
__device__ float g_hseq[2][SEQ][H];      // fwd/bwd hidden outputs (bwd kept in scan order)
__device__ float g_xgl[SEQ][8 * H];      // combined-LSTM gate pre-activations from comb input
__device__ float g_hl[SEQ][2 * H];       // combined-LSTM hidden outputs

// ---------------- f32x2 helpers ----------------
__device__ __forceinline__ u64 pk(float a, float b) {
    u64 r; asm("mov.b64 %0, {%1, %2};" : "=l"(r) : "f"(a), "f"(b)); return r;
}
__device__ __forceinline__ u64 fma2(u64 a, u64 b, u64 c) {
    u64 d; asm("fma.rn.f32x2 %0, %1, %2, %3;" : "=l"(d) : "l"(a), "l"(b), "l"(c)); return d;
}
__device__ __forceinline__ float2 unpk(u64 v) {
    float a, b; asm("mov.b64 {%0, %1}, %2;" : "=f"(a), "=f"(b) : "l"(v));
    return make_float2(a, b);
}
// fast activations: MUFU-based, err ~1e-6 (tolerance 1e-3; measured 3.9e-7)
__device__ __forceinline__ float sigf(float x) {
    return __fdividef(1.0f, 1.0f + __expf(-x));
}
__device__ __forceinline__ float tanhfast(float x) {
    float e = __expf(-2.0f * fabsf(x));            // in (0,1]; no overflow
    float r = __fdividef(1.0f - e, 1.0f + e);
    return copysignf(r, x);
}

__device__ __forceinline__ uint32_t smem_u32(const void* p) {
    uint32_t a;
    asm("{ .reg .u64 t; cvta.to.shared.u64 t, %1; cvt.u32.u64 %0, t; }" : "=r"(a) : "l"(p));
    return a;
}

// cluster-scope mbarrier wait (acquire.cluster)
#define MB_WAIT_CLUSTER(addr, par) do {                                          \
    uint32_t _d;                                                                 \
    asm volatile("{\n\t.reg .pred p;\n\t"                                        \
        "mbarrier.try_wait.parity.acquire.cluster.shared::cta.b64 p, [%1], %2;\n\t" \
        "selp.b32 %0, 1, 0, p;\n\t}"                                             \
        : "=r"(_d) : "r"(addr), "r"(par) : "memory");                            \
    if (!_d) {                                                                   \
        asm volatile("{\n\t.reg .pred P1;\n\t"                                   \
            "WL_%=:\n\t"                                                         \
            "mbarrier.try_wait.parity.acquire.cluster.shared::cta.b64 P1, [%0], %1, 0x989680;\n\t" \
            "@P1 bra.uni WD_%=;\n\t"                                             \
            "bra.uni WL_%=;\n\t"                                                 \
            "WD_%=:\n\t}"                                                        \
            :: "r"(addr), "r"(par) : "memory");                                  \
    }                                                                            \
} while (0)

// =====================================================================
// K0: x-projections for fwd/bwd LSTMs.
// grid = 40 blocks (dir*20+t), 512 threads (one gate row each).
// =====================================================================
__global__ void k_pre(const float* __restrict__ x,
                      const float* __restrict__ Wih_f, const float* __restrict__ bih_f,
                      const float* __restrict__ bhh_f,
                      const float* __restrict__ Wih_b, const float* __restrict__ bih_b,
                      const float* __restrict__ bhh_b)
{
    int bx  = blockIdx.x;
    int dir = bx / SEQ;
    int t   = bx % SEQ;
    int r   = threadIdx.x;              // 0..511 gate row

    __shared__ float4 xs[H / 4];
    if (r < H / 4)
        xs[r] = ((const float4*)(x + (dir ? (SEQ - 1 - t) : t) * H))[r];
    __syncthreads();

    const float* Wih = dir ? Wih_b : Wih_f;
    const float4* wr = (const float4*)(Wih + r * H);
    float acc = 0.f;
#pragma unroll
    for (int i = 0; i < H / 4; i++) {
        float4 w = __ldg(&wr[i]);
        float4 xv = xs[i];
        acc += w.x * xv.x + w.y * xv.y + w.z * xv.z + w.w * xv.w;
    }
    const float* bi = dir ? bih_b : bih_f;
    const float* bh = dir ? bhh_b : bhh_f;
    g_xg[dir][t][r] = acc + bi[r] + bh[r];
}

// =====================================================================
// K1: fwd + bwd recurrences. One block per direction.
// LAYOUT: q=tid&3 (gate i/f/g/o), cell=tid>>2. A cell's 4 gates sit in
// 4 adjacent lanes -> gate gather = 3 shfl_xor, activation in EVERY warp,
// c-state in registers. ONE __syncthreads per step (h publish), h double-
// buffered to kill the WAR race the second sync used to cover.
// Whh row: cols 0..63 in regs (f32x2), cols 64..127 in shared.
// =====================================================================
#define FB_WSH_BYTES (16 * 512 * 16)
#define FB_XG_BYTES  (SEQ * 512 * 4)
#define FB_SMEM (FB_WSH_BYTES + FB_XG_BYTES + 2 * 128 * 4)

__global__ void __launch_bounds__(512)
k_fb(const float* __restrict__ Whh_f, const float* __restrict__ Whh_b,
     const float* __restrict__ h0f, const float* __restrict__ c0f,
     const float* __restrict__ h0b, const float* __restrict__ c0b)
{
    extern __shared__ __align__(16) char smem[];
    ulonglong2* wsh  = (ulonglong2*)smem;                          // [16][512] (cols 64..127)
    float*      xgsh = (float*)(smem + FB_WSH_BYTES);              // [SEQ][512] by tid
    float*      hsh  = (float*)(smem + FB_WSH_BYTES + FB_XG_BYTES);// [2][128] double-buffered h

    int dir  = blockIdx.x;
    int tid  = threadIdx.x;
    int q    = tid & 3;                 // gate index (i,f,g,o)
    int cell = tid >> 2;                // 0..127
    int row  = q * H + cell;            // gate row in [0,512)

    const float* Whh = dir ? Whh_b : Whh_f;
    const float* h0  = dir ? h0b : h0f;
    const float* c0  = dir ? c0b : c0f;

    const float4* wr = (const float4*)(Whh + row * H);
    u64 wreg[32];
#pragma unroll
    for (int i = 0; i < 16; i++) {                 // cols 0..63 -> registers
        float4 w = __ldg(&wr[i]);
        wreg[2 * i]     = pk(w.x, w.y);
        wreg[2 * i + 1] = pk(w.z, w.w);
    }
#pragma unroll
    for (int m = 0; m < 16; m++) {                 // cols 64..127 -> shared
        float4 w = __ldg(&wr[16 + m]);
        wsh[m * 512 + tid] = make_ulonglong2(pk(w.x, w.y), pk(w.z, w.w));
    }
#pragma unroll
    for (int t = 0; t < SEQ; t++)                  // stage x-gates by (t, tid)
        xgsh[t * 512 + tid] = g_xg[dir][t][row];
    if (tid < H) hsh[tid] = h0[tid];               // buffer 0
    float creg = (q == 0) ? c0[cell] : 0.f;        // cell state lives in lane q==0
    __syncthreads();

    for (int t = 0; t < SEQ; t++) {
        const ulonglong2* h2p = (const ulonglong2*)(hsh + (t & 1) * 128);
        u64 acc0 = 0ull, acc1 = 0ull;
#pragma unroll
        for (int m = 0; m < 16; m++) {             // register-resident half
            ulonglong2 hv = h2p[m];
            acc0 = fma2(wreg[2 * m],     hv.x, acc0);
            acc1 = fma2(wreg[2 * m + 1], hv.y, acc1);
        }
#pragma unroll
        for (int m = 0; m < 16; m++) {             // shared half
            ulonglong2 hv = h2p[16 + m];
            ulonglong2 wv = wsh[m * 512 + tid];
            acc0 = fma2(wv.x, hv.x, acc0);
            acc1 = fma2(wv.y, hv.y, acc1);
        }
        float2 a = unpk(acc0), b = unpk(acc1);
        float s = a.x + a.y + b.x + b.y + xgsh[t * 512 + tid];
        // gather the cell's 4 gates into lane q==0 (3 shfls, warp-local)
        float gf = __shfl_xor_sync(0xFFFFFFFFu, s, 1);
        float gg = __shfl_xor_sync(0xFFFFFFFFu, s, 2);
        float go = __shfl_xor_sync(0xFFFFFFFFu, s, 3);
        if (q == 0) {
            float c2 = sigf(gf) * creg + sigf(s) * tanhfast(gg);
            float h2 = sigf(go) * tanhfast(c2);
            creg = c2;
            hsh[((t + 1) & 1) * 128 + cell] = h2;
            g_hseq[dir][t][cell] = h2;
        }
        __syncthreads();                            // publish h for next step
    }
}

// =====================================================================
// K2: combined-LSTM input projections: Wih_l @ concat(fwd,bwd) + biases.
// grid = (20 t) x (4 row-chunks), 256 threads (one of 1024 gate rows each).
// =====================================================================
__global__ void k_lpre(const float* __restrict__ Wih_l,
                       const float* __restrict__ bih_l, const float* __restrict__ bhh_l)
{
    int t     = blockIdx.x >> 2;
    int chunk = blockIdx.x & 3;
    int tid   = threadIdx.x;            // 0..255
    int row   = chunk * 256 + tid;

    __shared__ float cs[2 * H];
    if (tid < H) cs[tid] = g_hseq[0][t][tid];
    else         cs[tid] = g_hseq[1][t][tid - H];
    __syncthreads();

    const float4* wr = (const float4*)(Wih_l + row * 2 * H);
    const float4* cv = (const float4*)cs;
    float acc = 0.f;
#pragma unroll
    for (int i = 0; i < 64; i++) {
        float4 w = __ldg(&wr[i]);
        float4 h = cv[i];
        acc += w.x * h.x + w.y * h.y + w.z * h.z + w.w * h.w;
    }
    g_xgl[t][row] = acc + bih_l[row] + bhh_l[row];
}

// =====================================================================
// K3: combined recurrence (2H=256 cells, Whh_l = 1MB). 8 CTAs in ONE
// CLUSTER, 256 threads/CTA. Per cell: 8 lanes (4 gates x 2 k-halves),
// 128 cols/thread register-resident. Gate gather = 4 shfls (warp-local).
// h broadcast via mapa + st.shared::cluster; sync = two alternating
// mbarriers (count 256 = 32 activation lanes x 8 CTAs), arrive.release.
// cluster after stores, try_wait.parity.acquire.cluster before reads.
// NO barrier.cluster and NO __syncthreads in the loop. Warp-convergent
// shfls guarantee every lane's hbuf reads precede its warp's arrivals
// (WAR-safe with the double-buffered hbuf). A warp stuck at the wait for
// step t has not arrived at t, so no mbarrier can run 2 phases ahead
// (no parity ABA with 2 alternating mbarriers).
// =====================================================================
__global__ void __launch_bounds__(256) __cluster_dims__(8, 1, 1)
k_l(const float* __restrict__ Whh_l,
    const float* __restrict__ h0l, const float* __restrict__ c0l)
{
    int tid = threadIdx.x;
    uint32_t rank; asm("mov.u32 %0, %%cluster_ctarank;" : "=r"(rank));
    int cell_l = tid >> 3;              // 0..31 local cell
    int sub    = tid & 7;               // lane within cell group
    int q      = sub >> 1;              // gate 0..3
    int kh     = sub & 1;               // k-half 0..1
    int cell   = rank * 32 + cell_l;    // global cell 0..255
    int grow   = q * 256 + cell;        // gate row 0..1023
    int lr     = q * 32 + cell_l;       // local row 0..127

    __shared__ __align__(16) float hbuf[2][2 * H];  // double-buffered full h
    __shared__ float xgl_sh[SEQ][128];              // staged x-gates by local row
    __shared__ __align__(8) unsigned long long mbar[2];

    const float4* wr = (const float4*)(Whh_l + grow * 256 + kh * 128);
    u64 wreg[64];
#pragma unroll
    for (int i = 0; i < 32; i++) {
        float4 w = __ldg(&wr[i]);
        wreg[2 * i]     = pk(w.x, w.y);
        wreg[2 * i + 1] = pk(w.z, w.w);
    }
    for (int idx = tid; idx < SEQ * 128; idx += 256) {
        int t = idx >> 7, l = idx & 127;
        xgl_sh[t][l] = g_xgl[t][(l >> 5) * 256 + rank * 32 + (l & 31)];
    }
    hbuf[0][tid] = h0l[tid];                        // 256 threads exactly
    float creg = (sub == 0) ? c0l[cell] : 0.f;
    if (tid < 2) {
        uint32_t mb = smem_u32(&mbar[tid]);
        asm volatile("mbarrier.init.shared.b64 [%0], %1;" :: "r"(mb), "r"(256u) : "memory");
    }
    __syncthreads();
    // make mbarriers + initial state visible cluster-wide before any arrive
    asm volatile("barrier.cluster.arrive.aligned;" ::: "memory");
    asm volatile("barrier.cluster.wait.aligned;"   ::: "memory");

    for (int t = 0; t < SEQ; t++) {
        if (t > 0) {
            uint32_t mb = smem_u32(&mbar[(t - 1) & 1]);
            uint32_t par = ((t - 1) >> 1) & 1;
            MB_WAIT_CLUSTER(mb, par);
        }
        const float4* hp = (const float4*)(&hbuf[t & 1][kh * 128]);
        u64 acc0 = 0ull, acc1 = 0ull;
#pragma unroll
        for (int i = 0; i < 32; i++) {
            float4 h4 = hp[i];
            acc0 = fma2(wreg[2 * i],     pk(h4.x, h4.y), acc0);
            acc1 = fma2(wreg[2 * i + 1], pk(h4.z, h4.w), acc1);
        }
        float2 a = unpk(acc0), b = unpk(acc1);
        float s = a.x + a.y + b.x + b.y;
        if (kh == 0) s += xgl_sh[t][lr];
        s += __shfl_xor_sync(0xFFFFFFFFu, s, 1);    // reduce k-halves
        // gather gates into sub==0 (lanes ^2,^4,^6 hold f,g,o sums)
        float gf = __shfl_xor_sync(0xFFFFFFFFu, s, 2);
        float gg = __shfl_xor_sync(0xFFFFFFFFu, s, 4);
        float go = __shfl_xor_sync(0xFFFFFFFFu, s, 6);
        if (sub == 0) {
            float c2 = sigf(gf) * creg + sigf(s) * tanhfast(gg);
            float h2 = sigf(go) * tanhfast(c2);
            creg = c2;
            g_hl[t][cell] = h2;                     // for k_gemm
            if (t < SEQ - 1) {
                uint32_t hoff = smem_u32(&hbuf[(t + 1) & 1][cell]);
                uint32_t boff = smem_u32(&mbar[t & 1]);
#pragma unroll
                for (int rt = 0; rt < 8; rt++) {    // broadcast h to all CTAs
                    asm volatile("{\n\t.reg .b32 ra;\n\t"
                        "mapa.shared::cluster.u32 ra, %0, %1;\n\t"
                        "st.shared::cluster.f32 [ra], %2;\n\t}"
                        :: "r"(hoff), "r"(rt), "f"(h2) : "memory");
                }
#pragma unroll
                for (int rt = 0; rt < 8; rt++) {    // release-arrive everywhere
                    asm volatile("{\n\t.reg .b32 ra;\n\t"
                        "mapa.shared::cluster.u32 ra, %0, %1;\n\t"
                        "mbarrier.arrive.release.cluster.shared::cluster.b64 _, [ra];\n\t}"
                        :: "r"(boff), "r"(rt) : "memory");
                }
            }
        }
    }
}

// =====================================================================
// K4: out[t][n] = hl[t] . Wlin[n] + blin[n]   (20 x 100000)
// Issue-floor ~15us (8M warp-fma2) == DRAM floor ~13us (102MB).
// =====================================================================
__global__ void __launch_bounds__(256, 2)
k_gemm(const float* __restrict__ Wlin, const float* __restrict__ blin,
       float* __restrict__ out)
{
    __shared__ __align__(16) float2 fbp[10][256];   // fbp[tp][k] = (hl[2tp][k], hl[2tp+1][k])
    int tid = threadIdx.x;
#pragma unroll
    for (int i = 0; i < 10; i++) {
        int idx = i * 256 + tid;
        int tp = idx >> 8, k = idx & 255;
        fbp[tp][k] = make_float2(g_hl[2 * tp][k], g_hl[2 * tp + 1][k]);
    }
    __syncthreads();

    int warp = tid >> 5, lane = tid & 31;
    int rr = lane & 3, ks = lane >> 2;
    int rbase = blockIdx.x * 64 + warp * 8 + rr;
    int r0c = (rbase < NC)     ? rbase     : NC - 1;
    int r1c = (rbase + 4 < NC) ? rbase + 4 : NC - 1;
    const float4* wp0 = (const float4*)(Wlin + (size_t)r0c * 256 + ks * 4);
    const float4* wp1 = (const float4*)(Wlin + (size_t)r1c * 256 + ks * 4);

    u64 acc[2][10];
#pragma unroll
    for (int g = 0; g < 2; g++)
#pragma unroll
        for (int tp = 0; tp < 10; tp++) acc[g][tp] = 0ull;

    // triple-buffered weights: chunk c (wa), c+1 (wb), c+2 loading (wn)
    float4 wa[2], wb[2], wn[2];
    wa[0] = __ldg(wp0);     wa[1] = __ldg(wp1);
    wb[0] = __ldg(wp0 + 8); wb[1] = __ldg(wp1 + 8);
    wn[0] = wa[0];          wn[1] = wa[1];

#pragma unroll
    for (int c = 0; c < 8; c++) {
        if (c < 6) {                       // prefetch chunk c+2 (2-deep pipeline)
            wn[0] = __ldg(wp0 + (c + 2) * 8);
            wn[1] = __ldg(wp1 + (c + 2) * 8);
        }
        int k0 = c * 32 + ks * 4;
        u64 ws[2][4];
#pragma unroll
        for (int g = 0; g < 2; g++) {
            ws[g][0] = pk(wa[g].x, wa[g].x); ws[g][1] = pk(wa[g].y, wa[g].y);
            ws[g][2] = pk(wa[g].z, wa[g].z); ws[g][3] = pk(wa[g].w, wa[g].w);
        }
#pragma unroll
        for (int tp = 0; tp < 10; tp++) {
            ulonglong2 f01 = *(const ulonglong2*)&fbp[tp][k0];
            ulonglong2 f23 = *(const ulonglong2*)&fbp[tp][k0 + 2];
#pragma unroll
            for (int g = 0; g < 2; g++) {
                acc[g][tp] = fma2(ws[g][0], f01.x, acc[g][tp]);
                acc[g][tp] = fma2(ws[g][1], f01.y, acc[g][tp]);
                acc[g][tp] = fma2(ws[g][2], f23.x, acc[g][tp]);
                acc[g][tp] = fma2(ws[g][3], f23.y, acc[g][tp]);
            }
        }
        wa[0] = wb[0]; wa[1] = wb[1];
        wb[0] = wn[0]; wb[1] = wn[1];
    }

    // reduce across the 8 k-eighth lanes (xor 4,8,16), then write
#pragma unroll
    for (int g = 0; g < 2; g++) {
        int r = rbase + g * 4;
        float bv = (r < NC) ? __ldg(&blin[r]) : 0.f;
#pragma unroll
        for (int tp = 0; tp < 10; tp++) {
            float2 v = unpk(acc[g][tp]);
#pragma unroll
            for (int off = 4; off <= 16; off <<= 1) {
                v.x += __shfl_xor_sync(0xFFFFFFFFu, v.x, off);
                v.y += __shfl_xor_sync(0xFFFFFFFFu, v.y, off);
            }
            if (ks == 0 && r < NC) {
                out[(size_t)(2 * tp) * NC + r]     = v.x + bv;
                out[(size_t)(2 * tp + 1) * NC + r] = v.y + bv;
            }
        }
    }
}

// =====================================================================
extern "C" void kernel_launch(void* const* d_in, const int* in_sizes, int n_in,
                              void* d_out, int out_size)
{
    const float* x     = (const float*)d_in[0];
    const float* h0f   = (const float*)d_in[1];
    const float* c0f   = (const float*)d_in[2];
    const float* h0b   = (const float*)d_in[3];
    const float* c0b   = (const float*)d_in[4];
    const float* h0l   = (const float*)d_in[5];
    const float* c0l   = (const float*)d_in[6];
    const float* Wih_f = (const float*)d_in[7];
    const float* Whh_f = (const float*)d_in[8];
    const float* bih_f = (const float*)d_in[9];
    const float* bhh_f = (const float*)d_in[10];
    const float* Wih_b = (const float*)d_in[11];
    const float* Whh_b = (const float*)d_in[12];
    const float* bih_b = (const float*)d_in[13];
    const float* bhh_b = (const float*)d_in[14];
    const float* Wih_l = (const float*)d_in[15];
    const float* Whh_l = (const float*)d_in[16];
    const float* bih_l = (const float*)d_in[17];
    const float* bhh_l = (const float*)d_in[18];
    const float* Wlin  = (const float*)d_in[19];
    const float* blin  = (const float*)d_in[20];
    float* out = (float*)d_out;

    cudaFuncSetAttribute(k_fb, cudaFuncAttributeMaxDynamicSharedMemorySize, FB_SMEM);

    k_pre<<<2 * SEQ, 512>>>(x, Wih_f, bih_f, bhh_f, Wih_b, bih_b, bhh_b);
    k_fb<<<2, 512, FB_SMEM>>>(Whh_f, Whh_b, h0f, c0f, h0b, c0b);
    k_lpre<<<SEQ * 4, 256>>>(Wih_l, bih_l, bhh_l);
    k_l<<<8, 256>>>(Whh_l, h0l, c0l);
    k_gemm<<<(NC + 63) / 64, 256>>>(Wlin, blin, out);
}

// round 15
// speedup vs baseline: 1.0497x; 1.0497x over previous
#include <cuda_runtime.h>
#include <math.h>
#include <stdint.h>

#define SEQ 20
#define H   128
#define NC  100000

typedef unsigned long long u64;

// ---------------- device scratch (no allocations allowed) ----------------
__device__ float g_xg[2][SEQ][4 * H];    // fwd/bwd gate pre-activations from x (+both biases)
__device__ float g_hseq[2][SEQ][H];      // fwd/bwd hidden outputs (bwd kept in scan order)
__device__ float g_xgl[SEQ][8 * H];      // combined-LSTM gate pre-activations from comb input
__device__ float g_hl[SEQ][2 * H];       // combined-LSTM hidden outputs

// ---------------- f32x2 helpers ----------------
__device__ __forceinline__ u64 pk(float a, float b) {
    u64 r; asm("mov.b64 %0, {%1, %2};" : "=l"(r) : "f"(a), "f"(b)); return r;
}
__device__ __forceinline__ u64 fma2(u64 a, u64 b, u64 c) {
    u64 d; asm("fma.rn.f32x2 %0, %1, %2, %3;" : "=l"(d) : "l"(a), "l"(b), "l"(c)); return d;
}
__device__ __forceinline__ float2 unpk(u64 v) {
    float a, b; asm("mov.b64 {%0, %1}, %2;" : "=f"(a), "=f"(b) : "l"(v));
    return make_float2(a, b);
}
// fast activations: MUFU-based, err ~1e-6 (tolerance 1e-3; measured 3.9e-7)
__device__ __forceinline__ float sigf(float x) {
    return __fdividef(1.0f, 1.0f + __expf(-x));
}
__device__ __forceinline__ float tanhfast(float x) {
    float e = __expf(-2.0f * fabsf(x));            // in (0,1]; no overflow
    float r = __fdividef(1.0f - e, 1.0f + e);
    return copysignf(r, x);
}

__device__ __forceinline__ uint32_t smem_u32(const void* p) {
    uint32_t a;
    asm("{ .reg .u64 t; cvta.to.shared.u64 t, %1; cvt.u32.u64 %0, t; }" : "=r"(a) : "l"(p));
    return a;
}

// cluster-scope mbarrier wait (acquire.cluster)
#define MB_WAIT_CLUSTER(addr, par) do {                                          \
    uint32_t _d;                                                                 \
    asm volatile("{\n\t.reg .pred p;\n\t"                                        \
        "mbarrier.try_wait.parity.acquire.cluster.shared::cta.b64 p, [%1], %2;\n\t" \
        "selp.b32 %0, 1, 0, p;\n\t}"                                             \
        : "=r"(_d) : "r"(addr), "r"(par) : "memory");                            \
    if (!_d) {                                                                   \
        asm volatile("{\n\t.reg .pred P1;\n\t"                                   \
            "WL_%=:\n\t"                                                         \
            "mbarrier.try_wait.parity.acquire.cluster.shared::cta.b64 P1, [%0], %1, 0x989680;\n\t" \
            "@P1 bra.uni WD_%=;\n\t"                                             \
            "bra.uni WL_%=;\n\t"                                                 \
            "WD_%=:\n\t}"                                                        \
            :: "r"(addr), "r"(par) : "memory");                                  \
    }                                                                            \
} while (0)

// cta-scope mbarrier wait (acquire.cta) — for the local aggregation barrier
#define MB_WAIT_CTA(addr, par) do {                                              \
    uint32_t _d;                                                                 \
    asm volatile("{\n\t.reg .pred p;\n\t"                                        \
        "mbarrier.try_wait.parity.acquire.cta.shared::cta.b64 p, [%1], %2;\n\t"  \
        "selp.b32 %0, 1, 0, p;\n\t}"                                             \
        : "=r"(_d) : "r"(addr), "r"(par) : "memory");                            \
    if (!_d) {                                                                   \
        asm volatile("{\n\t.reg .pred P1;\n\t"                                   \
            "WL_%=:\n\t"                                                         \
            "mbarrier.try_wait.parity.acquire.cta.shared::cta.b64 P1, [%0], %1, 0x989680;\n\t" \
            "@P1 bra.uni WD_%=;\n\t"                                             \
            "bra.uni WL_%=;\n\t"                                                 \
            "WD_%=:\n\t}"                                                        \
            :: "r"(addr), "r"(par) : "memory");                                  \
    }                                                                            \
} while (0)

// =====================================================================
// K0: x-projections for fwd/bwd LSTMs.
// grid = 40 blocks (dir*20+t), 512 threads (one gate row each).
// =====================================================================
__global__ void k_pre(const float* __restrict__ x,
                      const float* __restrict__ Wih_f, const float* __restrict__ bih_f,
                      const float* __restrict__ bhh_f,
                      const float* __restrict__ Wih_b, const float* __restrict__ bih_b,
                      const float* __restrict__ bhh_b)
{
    int bx  = blockIdx.x;
    int dir = bx / SEQ;
    int t   = bx % SEQ;
    int r   = threadIdx.x;              // 0..511 gate row

    __shared__ float4 xs[H / 4];
    if (r < H / 4)
        xs[r] = ((const float4*)(x + (dir ? (SEQ - 1 - t) : t) * H))[r];
    __syncthreads();

    const float* Wih = dir ? Wih_b : Wih_f;
    const float4* wr = (const float4*)(Wih + r * H);
    float acc = 0.f;
#pragma unroll
    for (int i = 0; i < H / 4; i++) {
        float4 w = __ldg(&wr[i]);
        float4 xv = xs[i];
        acc += w.x * xv.x + w.y * xv.y + w.z * xv.z + w.w * xv.w;
    }
    const float* bi = dir ? bih_b : bih_f;
    const float* bh = dir ? bhh_b : bhh_f;
    g_xg[dir][t][r] = acc + bi[r] + bh[r];
}

// =====================================================================
// K1: fwd + bwd recurrences. One block per direction.
// LAYOUT: q=tid&3 (gate i/f/g/o), cell=tid>>2. Gate gather = 3 shfl_xor,
// activation in EVERY warp, c-state in registers. ONE __syncthreads per
// step, h double-buffered. Whh: cols 0..63 regs, 64..127 shared.
// =====================================================================
#define FB_WSH_BYTES (16 * 512 * 16)
#define FB_XG_BYTES  (SEQ * 512 * 4)
#define FB_SMEM (FB_WSH_BYTES + FB_XG_BYTES + 2 * 128 * 4)

__global__ void __launch_bounds__(512)
k_fb(const float* __restrict__ Whh_f, const float* __restrict__ Whh_b,
     const float* __restrict__ h0f, const float* __restrict__ c0f,
     const float* __restrict__ h0b, const float* __restrict__ c0b)
{
    extern __shared__ __align__(16) char smem[];
    ulonglong2* wsh  = (ulonglong2*)smem;                          // [16][512] (cols 64..127)
    float*      xgsh = (float*)(smem + FB_WSH_BYTES);              // [SEQ][512] by tid
    float*      hsh  = (float*)(smem + FB_WSH_BYTES + FB_XG_BYTES);// [2][128] double-buffered h

    int dir  = blockIdx.x;
    int tid  = threadIdx.x;
    int q    = tid & 3;                 // gate index (i,f,g,o)
    int cell = tid >> 2;                // 0..127
    int row  = q * H + cell;            // gate row in [0,512)

    const float* Whh = dir ? Whh_b : Whh_f;
    const float* h0  = dir ? h0b : h0f;
    const float* c0  = dir ? c0b : c0f;

    const float4* wr = (const float4*)(Whh + row * H);
    u64 wreg[32];
#pragma unroll
    for (int i = 0; i < 16; i++) {                 // cols 0..63 -> registers
        float4 w = __ldg(&wr[i]);
        wreg[2 * i]     = pk(w.x, w.y);
        wreg[2 * i + 1] = pk(w.z, w.w);
    }
#pragma unroll
    for (int m = 0; m < 16; m++) {                 // cols 64..127 -> shared
        float4 w = __ldg(&wr[16 + m]);
        wsh[m * 512 + tid] = make_ulonglong2(pk(w.x, w.y), pk(w.z, w.w));
    }
#pragma unroll
    for (int t = 0; t < SEQ; t++)                  // stage x-gates by (t, tid)
        xgsh[t * 512 + tid] = g_xg[dir][t][row];
    if (tid < H) hsh[tid] = h0[tid];               // buffer 0
    float creg = (q == 0) ? c0[cell] : 0.f;        // cell state lives in lane q==0
    __syncthreads();

    for (int t = 0; t < SEQ; t++) {
        const ulonglong2* h2p = (const ulonglong2*)(hsh + (t & 1) * 128);
        u64 acc0 = 0ull, acc1 = 0ull;
#pragma unroll
        for (int m = 0; m < 16; m++) {             // register-resident half
            ulonglong2 hv = h2p[m];
            acc0 = fma2(wreg[2 * m],     hv.x, acc0);
            acc1 = fma2(wreg[2 * m + 1], hv.y, acc1);
        }
#pragma unroll
        for (int m = 0; m < 16; m++) {             // shared half
            ulonglong2 hv = h2p[16 + m];
            ulonglong2 wv = wsh[m * 512 + tid];
            acc0 = fma2(wv.x, hv.x, acc0);
            acc1 = fma2(wv.y, hv.y, acc1);
        }
        float2 a = unpk(acc0), b = unpk(acc1);
        float s = a.x + a.y + b.x + b.y + xgsh[t * 512 + tid];
        // gather the cell's 4 gates into lane q==0 (3 shfls, warp-local)
        float gf = __shfl_xor_sync(0xFFFFFFFFu, s, 1);
        float gg = __shfl_xor_sync(0xFFFFFFFFu, s, 2);
        float go = __shfl_xor_sync(0xFFFFFFFFu, s, 3);
        if (q == 0) {
            float c2 = sigf(gf) * creg + sigf(s) * tanhfast(gg);
            float h2 = sigf(go) * tanhfast(c2);
            creg = c2;
            hsh[((t + 1) & 1) * 128 + cell] = h2;
            g_hseq[dir][t][cell] = h2;
        }
        __syncthreads();                            // publish h for next step
    }
}

// =====================================================================
// K2: combined-LSTM input projections: Wih_l @ concat(fwd,bwd) + biases.
// grid = (20 t) x (4 row-chunks), 256 threads (one of 1024 gate rows each).
// =====================================================================
__global__ void k_lpre(const float* __restrict__ Wih_l,
                       const float* __restrict__ bih_l, const float* __restrict__ bhh_l)
{
    int t     = blockIdx.x >> 2;
    int chunk = blockIdx.x & 3;
    int tid   = threadIdx.x;            // 0..255
    int row   = chunk * 256 + tid;

    __shared__ float cs[2 * H];
    if (tid < H) cs[tid] = g_hseq[0][t][tid];
    else         cs[tid] = g_hseq[1][t][tid - H];
    __syncthreads();

    const float4* wr = (const float4*)(Wih_l + row * 2 * H);
    const float4* cv = (const float4*)cs;
    float acc = 0.f;
#pragma unroll
    for (int i = 0; i < 64; i++) {
        float4 w = __ldg(&wr[i]);
        float4 h = cv[i];
        acc += w.x * h.x + w.y * h.y + w.z * h.z + w.w * h.w;
    }
    g_xgl[t][row] = acc + bih_l[row] + bhh_l[row];
}

// =====================================================================
// K3: combined recurrence (2H=256 cells, Whh_l = 1MB). 8 CTAs in ONE
// CLUSTER, 256 threads/CTA; 8 lanes/cell (4 gates x 2 k-halves),
// 128 cols/thread register-resident; gate gather = 4 shfls.
// HIERARCHICAL SYNC: per step, 32 activation lanes arrive (release) on a
// LOCAL agg barrier (count 32); tid0 acquires it (visibility of all
// lanes' remote h-stores via release->acquire transitivity) then issues
// ONE arrive per CTA on the 8 step barriers (count 8). Remote-arrival
// traffic per barrier: 256 -> 8 per step. Phases: agg[t&1]/stp[t&1],
// parity (t>>1)&1. No __syncthreads / barrier.cluster in the loop.
// =====================================================================
__global__ void __launch_bounds__(256) __cluster_dims__(8, 1, 1)
k_l(const float* __restrict__ Whh_l,
    const float* __restrict__ h0l, const float* __restrict__ c0l)
{
    int tid = threadIdx.x;
    uint32_t rank; asm("mov.u32 %0, %%cluster_ctarank;" : "=r"(rank));
    int cell_l = tid >> 3;              // 0..31 local cell
    int sub    = tid & 7;               // lane within cell group
    int q      = sub >> 1;              // gate 0..3
    int kh     = sub & 1;               // k-half 0..1
    int cell   = rank * 32 + cell_l;    // global cell 0..255
    int grow   = q * 256 + cell;        // gate row 0..1023
    int lr     = q * 32 + cell_l;       // local row 0..127

    __shared__ __align__(16) float hbuf[2][2 * H];  // double-buffered full h
    __shared__ float xgl_sh[SEQ][128];              // staged x-gates by local row
    __shared__ __align__(8) unsigned long long aggb[2];  // local agg (count 32)
    __shared__ __align__(8) unsigned long long stpb[2];  // step barrier (count 8)

    const float4* wr = (const float4*)(Whh_l + grow * 256 + kh * 128);
    u64 wreg[64];
#pragma unroll
    for (int i = 0; i < 32; i++) {
        float4 w = __ldg(&wr[i]);
        wreg[2 * i]     = pk(w.x, w.y);
        wreg[2 * i + 1] = pk(w.z, w.w);
    }
    for (int idx = tid; idx < SEQ * 128; idx += 256) {
        int t = idx >> 7, l = idx & 127;
        xgl_sh[t][l] = g_xgl[t][(l >> 5) * 256 + rank * 32 + (l & 31)];
    }
    hbuf[0][tid] = h0l[tid];                        // 256 threads exactly
    float creg = (sub == 0) ? c0l[cell] : 0.f;
    if (tid < 2) {
        uint32_t mb = smem_u32(&aggb[tid]);
        asm volatile("mbarrier.init.shared.b64 [%0], %1;" :: "r"(mb), "r"(32u) : "memory");
        uint32_t sb = smem_u32(&stpb[tid]);
        asm volatile("mbarrier.init.shared.b64 [%0], %1;" :: "r"(sb), "r"(8u) : "memory");
    }
    __syncthreads();
    // make barriers + initial state visible cluster-wide before any arrive
    asm volatile("barrier.cluster.arrive.aligned;" ::: "memory");
    asm volatile("barrier.cluster.wait.aligned;"   ::: "memory");

    for (int t = 0; t < SEQ; t++) {
        if (t > 0) {
            uint32_t sb = smem_u32(&stpb[(t - 1) & 1]);
            uint32_t par = ((t - 1) >> 1) & 1;
            MB_WAIT_CLUSTER(sb, par);
        }
        const float4* hp = (const float4*)(&hbuf[t & 1][kh * 128]);
        u64 acc0 = 0ull, acc1 = 0ull;
#pragma unroll
        for (int i = 0; i < 32; i++) {
            float4 h4 = hp[i];
            acc0 = fma2(wreg[2 * i],     pk(h4.x, h4.y), acc0);
            acc1 = fma2(wreg[2 * i + 1], pk(h4.z, h4.w), acc1);
        }
        float2 a = unpk(acc0), b = unpk(acc1);
        float s = a.x + a.y + b.x + b.y;
        if (kh == 0) s += xgl_sh[t][lr];
        s += __shfl_xor_sync(0xFFFFFFFFu, s, 1);    // reduce k-halves
        // gather gates into sub==0 (lanes ^2,^4,^6 hold f,g,o sums)
        float gf = __shfl_xor_sync(0xFFFFFFFFu, s, 2);
        float gg = __shfl_xor_sync(0xFFFFFFFFu, s, 4);
        float go = __shfl_xor_sync(0xFFFFFFFFu, s, 6);
        if (sub == 0) {
            float c2 = sigf(gf) * creg + sigf(s) * tanhfast(gg);
            float h2 = sigf(go) * tanhfast(c2);
            creg = c2;
            g_hl[t][cell] = h2;                     // for k_gemm
            if (t < SEQ - 1) {
                uint32_t hoff = smem_u32(&hbuf[(t + 1) & 1][cell]);
#pragma unroll
                for (int rt = 0; rt < 8; rt++) {    // broadcast h to all CTAs
                    asm volatile("{\n\t.reg .b32 ra;\n\t"
                        "mapa.shared::cluster.u32 ra, %0, %1;\n\t"
                        "st.shared::cluster.f32 [ra], %2;\n\t}"
                        :: "r"(hoff), "r"(rt), "f"(h2) : "memory");
                }
                // release my stores into the LOCAL agg barrier (count 32)
                uint32_t ab = smem_u32(&aggb[t & 1]);
                asm volatile(
                    "mbarrier.arrive.release.cta.shared::cta.b64 _, [%0];"
                    :: "r"(ab) : "memory");
            }
        }
        if (tid == 0 && t < SEQ - 1) {
            // acquire all 32 lanes' stores, then signal all 8 CTAs once each
            uint32_t ab = smem_u32(&aggb[t & 1]);
            MB_WAIT_CTA(ab, (t >> 1) & 1);
            uint32_t sb = smem_u32(&stpb[t & 1]);
#pragma unroll
            for (int rt = 0; rt < 8; rt++) {
                asm volatile("{\n\t.reg .b32 ra;\n\t"
                    "mapa.shared::cluster.u32 ra, %0, %1;\n\t"
                    "mbarrier.arrive.release.cluster.shared::cluster.b64 _, [ra];\n\t}"
                    :: "r"(sb), "r"(rt) : "memory");
            }
        }
    }
}

// =====================================================================
// K4: out[t][n] = hl[t] . Wlin[n] + blin[n]   (20 x 100000)
// Issue-floor ~15us (8M warp-fma2) == DRAM floor ~13us (102MB).
// =====================================================================
__global__ void __launch_bounds__(256, 2)
k_gemm(const float* __restrict__ Wlin, const float* __restrict__ blin,
       float* __restrict__ out)
{
    __shared__ __align__(16) float2 fbp[10][256];   // fbp[tp][k] = (hl[2tp][k], hl[2tp+1][k])
    int tid = threadIdx.x;
#pragma unroll
    for (int i = 0; i < 10; i++) {
        int idx = i * 256 + tid;
        int tp = idx >> 8, k = idx & 255;
        fbp[tp][k] = make_float2(g_hl[2 * tp][k], g_hl[2 * tp + 1][k]);
    }
    __syncthreads();

    int warp = tid >> 5, lane = tid & 31;
    int rr = lane & 3, ks = lane >> 2;
    int rbase = blockIdx.x * 64 + warp * 8 + rr;
    int r0c = (rbase < NC)     ? rbase     : NC - 1;
    int r1c = (rbase + 4 < NC) ? rbase + 4 : NC - 1;
    const float4* wp0 = (const float4*)(Wlin + (size_t)r0c * 256 + ks * 4);
    const float4* wp1 = (const float4*)(Wlin + (size_t)r1c * 256 + ks * 4);

    u64 acc[2][10];
#pragma unroll
    for (int g = 0; g < 2; g++)
#pragma unroll
        for (int tp = 0; tp < 10; tp++) acc[g][tp] = 0ull;

    // triple-buffered weights: chunk c (wa), c+1 (wb), c+2 loading (wn)
    float4 wa[2], wb[2], wn[2];
    wa[0] = __ldg(wp0);     wa[1] = __ldg(wp1);
    wb[0] = __ldg(wp0 + 8); wb[1] = __ldg(wp1 + 8);
    wn[0] = wa[0];          wn[1] = wa[1];

#pragma unroll
    for (int c = 0; c < 8; c++) {
        if (c < 6) {                       // prefetch chunk c+2 (2-deep pipeline)
            wn[0] = __ldg(wp0 + (c + 2) * 8);
            wn[1] = __ldg(wp1 + (c + 2) * 8);
        }
        int k0 = c * 32 + ks * 4;
        u64 ws[2][4];
#pragma unroll
        for (int g = 0; g < 2; g++) {
            ws[g][0] = pk(wa[g].x, wa[g].x); ws[g][1] = pk(wa[g].y, wa[g].y);
            ws[g][2] = pk(wa[g].z, wa[g].z); ws[g][3] = pk(wa[g].w, wa[g].w);
        }
#pragma unroll
        for (int tp = 0; tp < 10; tp++) {
            ulonglong2 f01 = *(const ulonglong2*)&fbp[tp][k0];
            ulonglong2 f23 = *(const ulonglong2*)&fbp[tp][k0 + 2];
#pragma unroll
            for (int g = 0; g < 2; g++) {
                acc[g][tp] = fma2(ws[g][0], f01.x, acc[g][tp]);
                acc[g][tp] = fma2(ws[g][1], f01.y, acc[g][tp]);
                acc[g][tp] = fma2(ws[g][2], f23.x, acc[g][tp]);
                acc[g][tp] = fma2(ws[g][3], f23.y, acc[g][tp]);
            }
        }
        wa[0] = wb[0]; wa[1] = wb[1];
        wb[0] = wn[0]; wb[1] = wn[1];
    }

    // reduce across the 8 k-eighth lanes (xor 4,8,16), then write
#pragma unroll
    for (int g = 0; g < 2; g++) {
        int r = rbase + g * 4;
        float bv = (r < NC) ? __ldg(&blin[r]) : 0.f;
#pragma unroll
        for (int tp = 0; tp < 10; tp++) {
            float2 v = unpk(acc[g][tp]);
#pragma unroll
            for (int off = 4; off <= 16; off <<= 1) {
                v.x += __shfl_xor_sync(0xFFFFFFFFu, v.x, off);
                v.y += __shfl_xor_sync(0xFFFFFFFFu, v.y, off);
            }
            if (ks == 0 && r < NC) {
                out[(size_t)(2 * tp) * NC + r]     = v.x + bv;
                out[(size_t)(2 * tp + 1) * NC + r] = v.y + bv;
            }
        }
    }
}

// =====================================================================
extern "C" void kernel_launch(void* const* d_in, const int* in_sizes, int n_in,
                              void* d_out, int out_size)
{
    const float* x     = (const float*)d_in[0];
    const float* h0f   = (const float*)d_in[1];
    const float* c0f   = (const float*)d_in[2];
    const float* h0b   = (const float*)d_in[3];
    const float* c0b   = (const float*)d_in[4];
    const float* h0l   = (const float*)d_in[5];
    const float* c0l   = (const float*)d_in[6];
    const float* Wih_f = (const float*)d_in[7];
    const float* Whh_f = (const float*)d_in[8];
    const float* bih_f = (const float*)d_in[9];
    const float* bhh_f = (const float*)d_in[10];
    const float* Wih_b = (const float*)d_in[11];
    const float* Whh_b = (const float*)d_in[12];
    const float* bih_b = (const float*)d_in[13];
    const float* bhh_b = (const float*)d_in[14];
    const float* Wih_l = (const float*)d_in[15];
    const float* Whh_l = (const float*)d_in[16];
    const float* bih_l = (const float*)d_in[17];
    const float* bhh_l = (const float*)d_in[18];
    const float* Wlin  = (const float*)d_in[19];
    const float* blin  = (const float*)d_in[20];
    float* out = (float*)d_out;

    cudaFuncSetAttribute(k_fb, cudaFuncAttributeMaxDynamicSharedMemorySize, FB_SMEM);

    k_pre<<<2 * SEQ, 512>>>(x, Wih_f, bih_f, bhh_f, Wih_b, bih_b, bhh_b);
    k_fb<<<2, 512, FB_SMEM>>>(Whh_f, Whh_b, h0f, c0f, h0b, c0b);
    k_lpre<<<SEQ * 4, 256>>>(Wih_l, bih_l, bhh_l);
    k_l<<<8, 256>>>(Whh_l, h0l, c0l);
    k_gemm<<<(NC + 63) / 64, 256>>>(Wlin, blin, out);
}